// round 3
// baseline (speedup 1.0000x reference)
#include <cuda_runtime.h>

// Problem shapes (fixed by the dataset problem)
#define BB 8
#define CC 64
#define HH 256
#define WW 256
#define HW (HH*WW)       // 65536
#define HW4 (HW/4)       // 16384

// Scratch: 2 MB gray + 2 MB att (stores 1 + sigmoid(...))
__device__ float g_gray[BB*HW];
__device__ float g_att[BB*HW];

// ---------------------------------------------------------------------------
// K1: channel mean.  gray[b,h,w] = mean_c x[b,c,h,w].  float4 vectorized.
// ---------------------------------------------------------------------------
__global__ void __launch_bounds__(256) gray_kernel(const float* __restrict__ x) {
    int t = blockIdx.x * blockDim.x + threadIdx.x;   // [0, BB*HW4)
    if (t >= BB * HW4) return;
    int b = t >> 14;           // / 16384
    int p = t & (HW4 - 1);
    const float4* base = ((const float4*)x) + (size_t)b * CC * HW4 + p;

    float4 a0 = make_float4(0.f, 0.f, 0.f, 0.f);
    float4 a1 = make_float4(0.f, 0.f, 0.f, 0.f);
    float4 a2 = make_float4(0.f, 0.f, 0.f, 0.f);
    float4 a3 = make_float4(0.f, 0.f, 0.f, 0.f);
    #pragma unroll 4
    for (int c = 0; c < CC; c += 4) {
        float4 v0 = __ldg(base + (c + 0) * HW4);
        float4 v1 = __ldg(base + (c + 1) * HW4);
        float4 v2 = __ldg(base + (c + 2) * HW4);
        float4 v3 = __ldg(base + (c + 3) * HW4);
        a0.x += v0.x; a0.y += v0.y; a0.z += v0.z; a0.w += v0.w;
        a1.x += v1.x; a1.y += v1.y; a1.z += v1.z; a1.w += v1.w;
        a2.x += v2.x; a2.y += v2.y; a2.z += v2.z; a2.w += v2.w;
        a3.x += v3.x; a3.y += v3.y; a3.z += v3.z; a3.w += v3.w;
    }
    const float s = 1.0f / (float)CC;
    float4 o;
    o.x = (a0.x + a1.x + a2.x + a3.x) * s;
    o.y = (a0.y + a1.y + a2.y + a3.y) * s;
    o.z = (a0.z + a1.z + a2.z + a3.z) * s;
    o.w = (a0.w + a1.w + a2.w + a3.w) * s;
    ((float4*)g_gray)[t] = o;
}

// ---------------------------------------------------------------------------
// K2: DoG(5x5, zero-pad) -> Sobel(3x3, zero-pad on DoG) -> mag -> sigmoid gate.
// One 32x32 output tile per block.  Gray tile + halo(3) in smem; DoG tile +
// halo(1) in smem with out-of-image DoG forced to 0 (matches sequential-conv
// zero padding exactly, including the border frame).
// Stores att = 1 + sigmoid(mag*gw + gb).
// ---------------------------------------------------------------------------
__global__ void __launch_bounds__(1024) att_kernel(const float* __restrict__ gw,
                                                   const float* __restrict__ gbv) {
    __shared__ float sg[38][40];   // gray tile + halo 3 (padded cols)
    __shared__ float sd[34][36];   // dog tile + halo 1
    __shared__ float kd[25];       // DoG weights (gk1 - gk2)

    const int tx = threadIdx.x, ty = threadIdx.y;
    const int tid = ty * 32 + tx;

    if (tid == 0) {
        // Build normalized gaussian kernels exactly like the reference (fp32).
        float w1[25], w2[25];
        float s1 = 0.f, s2 = 0.f;
        #pragma unroll
        for (int i = 0; i < 25; ++i) {
            float dx = (float)(i / 5) - 2.0f;
            float dy = (float)(i % 5) - 2.0f;
            float r2 = dx * dx + dy * dy;
            float a = expf(-r2 * 0.5f);     // sigma = 1
            float b = expf(-r2 * 0.125f);   // sigma = 2
            w1[i] = a; w2[i] = b;
            s1 += a;  s2 += b;
        }
        float i1 = 1.0f / s1, i2 = 1.0f / s2;
        #pragma unroll
        for (int i = 0; i < 25; ++i) kd[i] = w1[i] * i1 - w2[i] * i2;
    }

    const int b  = blockIdx.z;
    const int y0 = blockIdx.y * 32;
    const int x0 = blockIdx.x * 32;
    const float* gray = g_gray + (size_t)b * HW;

    __syncthreads();   // kd ready before use; also fences before sg writes reuse

    // Load gray tile + halo(3), zero outside image.
    for (int i = tid; i < 38 * 38; i += 1024) {
        int r = i / 38, c = i % 38;
        int gy = y0 - 3 + r, gx = x0 - 3 + c;
        float v = 0.f;
        if ((unsigned)gy < HH && (unsigned)gx < WW) v = gray[gy * WW + gx];
        sg[r][c] = v;
    }
    __syncthreads();

    // DoG on tile + halo(1); out-of-image DoG positions are 0 (Sobel zero-pad).
    for (int i = tid; i < 34 * 34; i += 1024) {
        int r = i / 34, c = i % 34;
        int gy = y0 - 1 + r, gx = x0 - 1 + c;
        float v = 0.f;
        if ((unsigned)gy < HH && (unsigned)gx < WW) {
            float acc = 0.f;
            #pragma unroll
            for (int ki = 0; ki < 5; ++ki)
                #pragma unroll
                for (int kj = 0; kj < 5; ++kj)
                    acc += kd[ki * 5 + kj] * sg[r + ki][c + kj];
            v = acc;
        }
        sd[r][c] = v;
    }
    __syncthreads();

    // Sobel (correlation; sign irrelevant under the magnitude).
    float d00 = sd[ty    ][tx    ], d01 = sd[ty    ][tx + 1], d02 = sd[ty    ][tx + 2];
    float d10 = sd[ty + 1][tx    ],                            d12 = sd[ty + 1][tx + 2];
    float d20 = sd[ty + 2][tx    ], d21 = sd[ty + 2][tx + 1], d22 = sd[ty + 2][tx + 2];
    float gxv = (d02 - d00) + 2.0f * (d12 - d10) + (d22 - d20);
    float gyv = (d20 - d00) + 2.0f * (d21 - d01) + (d22 - d02);
    float mag = sqrtf(gxv * gxv + gyv * gyv + 1e-6f);
    float tv  = mag * gw[0] + gbv[0];
    float att = 1.0f / (1.0f + expf(-tv));
    g_att[(size_t)b * HW + (y0 + ty) * WW + (x0 + tx)] = 1.0f + att;
}

// ---------------------------------------------------------------------------
// K3: out[b,c,h,w] = x[b,c,h,w] * att[b,h,w]   (att already holds 1+sigmoid)
// ---------------------------------------------------------------------------
__global__ void __launch_bounds__(256) apply_kernel(const float* __restrict__ x,
                                                    float* __restrict__ out) {
    int t = blockIdx.x * blockDim.x + threadIdx.x;   // float4 index
    if (t >= BB * CC * HW4) return;
    int b = t >> 20;                 // / (CC*HW4) = / 2^20
    int p = t & (HW4 - 1);
    float4 a = __ldg(((const float4*)g_att) + b * HW4 + p);
    float4 v = __ldg(((const float4*)x) + t);
    v.x *= a.x; v.y *= a.y; v.z *= a.z; v.w *= a.w;
    ((float4*)out)[t] = v;
}

// ---------------------------------------------------------------------------
extern "C" void kernel_launch(void* const* d_in, const int* in_sizes, int n_in,
                              void* d_out, int out_size) {
    const float* x  = (const float*)d_in[0];
    const float* gw = (const float*)d_in[1];
    const float* gb = (const float*)d_in[2];
    float* out = (float*)d_out;

    // K1: 131072 threads
    gray_kernel<<<(BB * HW4 + 255) / 256, 256>>>(x);

    // K2: one 32x32 tile per block
    dim3 gridA(WW / 32, HH / 32, BB);
    dim3 blockA(32, 32);
    att_kernel<<<gridA, blockA>>>(gw, gb);

    // K3: 8388608 float4 threads
    apply_kernel<<<(BB * CC * HW4 + 255) / 256, 256>>>(x, out);
}